// round 6
// baseline (speedup 1.0000x reference)
#include <cuda_runtime.h>
#include <cuda_bf16.h>
#include <cstdint>

// GraphAttentionPooling — 256-bit load/store version (sm_100 LDG.E.256).
//   x: [B=196608, F=256] f32, G=65536 groups of P=3 rows.
//   out[g,f] = sum_p softmax_p(dot(x[g,p,:],w))[p] * x[g,p,f]
//
// One warp per group. Lane l owns floats [8l, 8l+8) of each 256-float row:
// exactly one ld.global.v8.f32 per row (3 loads) and one st.global.v8.f32
// for the output row. Tests whether wider requests lift achieved DRAM BW
// past the ~6.2 TB/s plateau seen across R1-R3.

#define F 256
#define P 3
#define WARPS_PER_BLOCK 8
#define THREADS (WARPS_PER_BLOCK * 32)

// 256-bit global load (read-only path).
#define LDG256(d, ptr)                                                        \
    asm volatile("ld.global.nc.v8.f32 {%0,%1,%2,%3,%4,%5,%6,%7}, [%8];"       \
                 : "=f"(d[0]), "=f"(d[1]), "=f"(d[2]), "=f"(d[3]),            \
                   "=f"(d[4]), "=f"(d[5]), "=f"(d[6]), "=f"(d[7])             \
                 : "l"(ptr))

// 256-bit global store.
#define STG256(ptr, s)                                                        \
    asm volatile("st.global.v8.f32 [%0], {%1,%2,%3,%4,%5,%6,%7,%8};"          \
                 :: "l"(ptr),                                                 \
                    "f"(s[0]), "f"(s[1]), "f"(s[2]), "f"(s[3]),               \
                    "f"(s[4]), "f"(s[5]), "f"(s[6]), "f"(s[7])                \
                 : "memory")

__global__ __launch_bounds__(THREADS)
void gap_kernel(const float* __restrict__ x,
                const float* __restrict__ w,
                float* __restrict__ out,
                int G)
{
    const int gid  = (blockIdx.x * WARPS_PER_BLOCK) + (threadIdx.x >> 5);
    const int lane = threadIdx.x & 31;
    if (gid >= G) return;

    const float* xr = x + (size_t)gid * (size_t)(P * F) + lane * 8;

    // Front-batch all global loads: 3 LDG.256 + 1 weight LDG.256.
    float r0[8], r1[8], r2[8], wv[8];
    LDG256(r0, xr);
    LDG256(r1, xr + F);
    LDG256(r2, xr + 2 * F);
    LDG256(wv, w + lane * 8);

    // Per-row partial dot products over this lane's 8 elements.
    float d0 = 0.f, d1 = 0.f, d2 = 0.f;
    #pragma unroll
    for (int i = 0; i < 8; i++) {
        d0 = fmaf(r0[i], wv[i], d0);
        d1 = fmaf(r1[i], wv[i], d1);
        d2 = fmaf(r2[i], wv[i], d2);
    }

    // Warp butterfly reduce (all three dots share the butterfly passes).
    #pragma unroll
    for (int off = 16; off > 0; off >>= 1) {
        d0 += __shfl_xor_sync(0xffffffffu, d0, off);
        d1 += __shfl_xor_sync(0xffffffffu, d1, off);
        d2 += __shfl_xor_sync(0xffffffffu, d2, off);
    }

    // 3-way softmax (bias cancels; subtract max for stability).
    float m  = fmaxf(d0, fmaxf(d1, d2));
    float e0 = __expf(d0 - m);
    float e1 = __expf(d1 - m);
    float e2 = __expf(d2 - m);
    float inv = 1.0f / (e0 + e1 + e2);
    float a0 = e0 * inv, a1 = e1 * inv, a2 = e2 * inv;

    // Weighted sum of the three rows -> one STG.256.
    float o[8];
    #pragma unroll
    for (int i = 0; i < 8; i++)
        o[i] = fmaf(r0[i], a0, fmaf(r1[i], a1, r2[i] * a2));

    float* op = out + (size_t)gid * F + lane * 8;
    STG256(op, o);
}

extern "C" void kernel_launch(void* const* d_in, const int* in_sizes, int n_in,
                              void* d_out, int out_size)
{
    const float* x = (const float*)d_in[0];   // batch_rep [196608, 256]
    const float* w = (const float*)d_in[1];   // W_weight  [1, 256]
    // d_in[2] = W_bias [1] — softmax-invariant, unused.
    float* out = (float*)d_out;               // [65536, 256]

    const int B = in_sizes[0] / F;            // 196608
    const int G = B / P;                      // 65536

    const int blocks = (G + WARPS_PER_BLOCK - 1) / WARPS_PER_BLOCK;
    gap_kernel<<<blocks, THREADS>>>(x, w, out, G);
}